// round 16
// baseline (speedup 1.0000x reference)
#include <cuda_runtime.h>
#include <cuda_fp16.h>
#include <math.h>
#include <stdint.h>

#define TD 1024
#define TE 64
#define BM 32            // tokens per CTA (grid = 512)
#define THREADS 256
#define DEPTH 4          // per-warp A ring slots (1KB each)

// smem layout:
//   A ring: wid*4096 + slot*1024, 8 warps x 4KB : 0 .. 32768
//   Cs [32][66] f32 (aliases ring post-mainloop): 0 .. 8448
//   noiseS [32][64] f32                         : 32768 .. 40960
//   nws [64] f32                                : 40960 .. 41216
//   w1s/w2s/i1s/i2s (32 each)                   : 41216 .. 41728
#define CS_STRIDE 66
#define NZ_OFF    32768
#define NW_OFF    40960
#define W1_OFF    41216
#define W2_OFF    41344
#define I1_OFF    41472
#define I2_OFF    41600
#define SMEM_BYTES 41728

typedef unsigned int u32;

// W fragments, k-permuted, split by term: [kstep][n8tile][lane] -> uint2{b0,b1}
__device__ uint2 g_wfH[16384];
__device__ uint2 g_wfL[16384];

__device__ __forceinline__ u32 smem_u32(const void* p) {
    u32 a;
    asm("{ .reg .u64 t; cvta.to.shared.u64 t, %1; cvt.u32.u64 %0, t; }" : "=r"(a) : "l"(p));
    return a;
}
// 2 floats -> 2 packed fp16x2 terms (hi, residual-lo)
__device__ __forceinline__ void split2(float vl, float vh, u32& t0, u32& t1) {
    __half2 h0 = __floats2half2_rn(vl, vh);
    float2 f0 = __half22float2(h0);
    __half2 h1 = __floats2half2_rn(vl - f0.x, vh - f0.y);
    t0 = *reinterpret_cast<u32*>(&h0);
    t1 = *reinterpret_cast<u32*>(&h1);
}
__device__ __forceinline__ void mma16816(float* c, const u32* A, u32 b0, u32 b1) {
    asm volatile(
        "mma.sync.aligned.m16n8k16.row.col.f32.f16.f16.f32 "
        "{%0,%1,%2,%3}, {%4,%5,%6,%7}, {%8,%9}, {%0,%1,%2,%3};"
        : "+f"(c[0]), "+f"(c[1]), "+f"(c[2]), "+f"(c[3])
        : "r"(A[0]), "r"(A[1]), "r"(A[2]), "r"(A[3]), "r"(b0), "r"(b1));
}
__device__ __forceinline__ void cp16(u32 dst, const void* src) {
    asm volatile("cp.async.cg.shared.global [%0], [%1], 16;" :: "r"(dst), "l"(src));
}
__device__ __forceinline__ void cp_commit() {
    asm volatile("cp.async.commit_group;" ::: "memory");
}
__device__ __forceinline__ void cp_wait2() {
    asm volatile("cp.async.wait_group 2;" ::: "memory");
}
__device__ __forceinline__ float4 lds128(u32 a) {
    float4 v;
    asm volatile("ld.shared.v4.f32 {%0,%1,%2,%3}, [%4];"
                 : "=f"(v.x), "=f"(v.y), "=f"(v.z), "=f"(v.w) : "r"(a));
    return v;
}

// ---------------- pre-kernel: W fp32 -> k-permuted fp16x2 fragments (hi/lo split) ----------------
__global__ void __launch_bounds__(256) wconv_kernel(const float* __restrict__ gw) {
    int t = blockIdx.x * 256 + threadIdx.x;     // 0..16383
    int ks   = t >> 8;
    int nt   = (t >> 5) & 7;
    int lane = t & 31;
    int n  = nt * 8 + (lane >> 2);
    int k0 = ks * 16 + 4 * (lane & 3);          // 4 contiguous k per lane (pi-permuted)
    float4 p = *reinterpret_cast<const float4*>(gw + n * TD + k0);
    u32 b0h, b0l, b1h, b1l;
    split2(p.x, p.y, b0h, b0l);
    split2(p.z, p.w, b1h, b1l);
    int idx = ks * 256 + nt * 32 + lane;
    g_wfH[idx] = make_uint2(b0h, b1h);
    g_wfL[idx] = make_uint2(b0l, b1l);
}

// ---------------- main fused kernel ----------------
// warp = 16 tokens x 32 experts x K/2.  8 warps: mtw(2) x nh(2) x kh(2).
__global__ void __launch_bounds__(THREADS, 3) gate_kernel(
    const float* __restrict__ x,      // [T, 1024]
    const float* __restrict__ nw,     // [64]
    const float* __restrict__ noise,  // [T, 64]
    float* __restrict__ out,
    int T, int write_idx)
{
    extern __shared__ char smem[];
    const u32 sb = smem_u32(smem);
    const int tid  = threadIdx.x;
    const int lane = tid & 31;
    const int wid  = tid >> 5;
    const int mtw  = wid & 1;          // token group: tokens mtw*16..+15
    const int nh   = (wid >> 1) & 1;   // expert half: experts nh*32..+31
    const int kh   = wid >> 2;         // k half: ksteps kh*32..+31
    const long long t0 = (long long)blockIdx.x * BM;

    // --- stage noise + nw into smem (hides epilogue tail) ---
    {
        const float4* np = reinterpret_cast<const float4*>(noise + t0 * TE);
        float4* ns = reinterpret_cast<float4*>(smem + NZ_OFF);
        #pragma unroll
        for (int u = 0; u < 2; u++) ns[u * 256 + tid] = np[u * 256 + tid];
        if (tid < TE) reinterpret_cast<float*>(smem + NW_OFF)[tid] = nw[tid];
    }

    const int kb = kh * 32;            // base kstep for this warp
    // A slot = 64 chunks of 16B; chunk c <-> row c>>2, quad c&3.
    // Lane copies chunks c0=lane (rows 0-7), c1=lane+32 (rows 8-15);
    // reader lane reads exactly its own chunks -> no intra-warp sync.
    const int c0 = lane, c1 = lane + 32;
    const float* xsrc0 = x + (t0 + mtw * 16 + (c0 >> 2)) * TD + kb * 16 + (c0 & 3) * 4;
    const float* xsrc1 = x + (t0 + mtw * 16 + 8 + ((c1 - 32) >> 2)) * TD + kb * 16 + (c1 & 3) * 4;
    const u32 ringBase = sb + wid * (DEPTH * 1024);
    const u32 ring0 = ringBase + c0 * 16;
    const u32 ring1 = ringBase + c1 * 16;
    const u32 ldsA = ringBase + (lane >> 2) * 64 + (lane & 3) * 16;
    const uint2* bpH = g_wfH + kb * 256 + nh * 128 + lane;
    const uint2* bpL = g_wfL + kb * 256 + nh * 128 + lane;

    float acc[4][4];
    #pragma unroll
    for (int i = 0; i < 4; i++)
        #pragma unroll
        for (int j = 0; j < 4; j++) acc[i][j] = 0.0f;

    // prologue: issue A slots 0..2
    #pragma unroll
    for (int p = 0; p < DEPTH - 1; p++) {
        cp16(ring0 + p * 1024, xsrc0 + p * 16);
        cp16(ring1 + p * 1024, xsrc1 + p * 16);
        cp_commit();
    }
    // preload B kstep kb (both terms, 4 n-tiles each)
    uint2 bH[4], bL[4];
    #pragma unroll
    for (int j = 0; j < 4; j++) bH[j] = bpH[j * 32];
    #pragma unroll
    for (int j = 0; j < 4; j++) bL[j] = bpL[j * 32];

    #pragma unroll 2
    for (int ks = 0; ks < 32; ks++) {
        cp_wait2();
        const u32 slot = ldsA + (ks & (DEPTH - 1)) * 1024;
        float4 fa = lds128(slot);            // row g,   k quad
        float4 fb = lds128(slot + 8 * 64);   // row g+8, k quad
        if (ks + DEPTH - 1 < 32) {
            cp16(ring0 + ((ks + DEPTH - 1) & (DEPTH - 1)) * 1024, xsrc0 + (ks + DEPTH - 1) * 16);
            cp16(ring1 + ((ks + DEPTH - 1) & (DEPTH - 1)) * 1024, xsrc1 + (ks + DEPTH - 1) * 16);
        }
        cp_commit();
        // convert A (both terms); a0=(g,klo) a1=(g+8,klo) a2=(g,khi) a3=(g+8,khi)
        u32 aH[4], aL[4];
        split2(fa.x, fa.y, aH[0], aL[0]);
        split2(fb.x, fb.y, aH[1], aL[1]);
        split2(fa.z, fa.w, aH[2], aL[2]);
        split2(fb.z, fb.w, aH[3], aL[3]);

        const int nks = (ks + 1) & 31;       // wraps harmlessly on last iter
        // pass 1: hh
        #pragma unroll
        for (int nt = 0; nt < 4; nt++) mma16816(acc[nt], aH, bH[nt].x, bH[nt].y);
        // pass 2: lh — last use of bH(ks)
        #pragma unroll
        for (int nt = 0; nt < 4; nt++) mma16816(acc[nt], aL, bH[nt].x, bH[nt].y);
        // reload bH <- kstep ks+1
        {
            const uint2* bq = bpH + nks * 256;
            #pragma unroll
            for (int j = 0; j < 4; j++) bH[j] = bq[j * 32];
        }
        // pass 3: hl — last use of bL(ks)
        #pragma unroll
        for (int nt = 0; nt < 4; nt++) mma16816(acc[nt], aH, bL[nt].x, bL[nt].y);
        // reload bL <- kstep ks+1
        {
            const uint2* bq = bpL + nks * 256;
            #pragma unroll
            for (int j = 0; j < 4; j++) bL[j] = bq[j * 32];
        }
    }

    // ---------------- split-K reduction (single plane) + epilogue ----------------
    __syncthreads();   // all warps done with ring before Cs overwrites it
    float* Cs  = reinterpret_cast<float*>(smem);
    float* w1s = reinterpret_cast<float*>(smem + W1_OFF);
    float* w2s = reinterpret_cast<float*>(smem + W2_OFF);
    int*   i1s = reinterpret_cast<int*>(smem + I1_OFF);
    int*   i2s = reinterpret_cast<int*>(smem + I2_OFF);
    const float* nzS  = reinterpret_cast<const float*>(smem + NZ_OFF);
    const float* nwsS = reinterpret_cast<const float*>(smem + NW_OFF);

    const int g  = lane >> 2, tq = lane & 3;
    const int r0 = mtw * 16 + g;
    const int cb = nh * 32;

    if (kh == 1) {   // kh=1 warps store their partial first
        #pragma unroll
        for (int nt = 0; nt < 4; nt++) {
            int col = cb + nt * 8 + 2 * tq;
            *reinterpret_cast<float2*>(&Cs[r0 * CS_STRIDE + col])       = make_float2(acc[nt][0], acc[nt][1]);
            *reinterpret_cast<float2*>(&Cs[(r0 + 8) * CS_STRIDE + col]) = make_float2(acc[nt][2], acc[nt][3]);
        }
    }
    __syncthreads();
    if (kh == 0) {   // kh=0 warps add theirs
        #pragma unroll
        for (int nt = 0; nt < 4; nt++) {
            int col = cb + nt * 8 + 2 * tq;
            float2* p0 = reinterpret_cast<float2*>(&Cs[r0 * CS_STRIDE + col]);
            float2* p1 = reinterpret_cast<float2*>(&Cs[(r0 + 8) * CS_STRIDE + col]);
            float2 v0 = *p0, v1 = *p1;
            v0.x += acc[nt][0]; v0.y += acc[nt][1];
            v1.x += acc[nt][2]; v1.y += acc[nt][3];
            *p0 = v0; *p1 = v1;
        }
    }
    __syncthreads();

    if (tid < BM) {
        const float* rowp = Cs + tid * CS_STRIDE;
        const float* nr   = nzS + tid * TE;
        float v1 = -3.402823466e38f, v2 = -3.402823466e38f;
        int i1 = 0, i2 = 0;
        #pragma unroll
        for (int e = 0; e < TE; e++) {
            float v = rowp[e] + nr[e] * nwsS[e];
            if (v > v1)      { v2 = v1; i2 = i1; v1 = v; i1 = e; }
            else if (v > v2) { v2 = v;  i2 = e; }
        }
        float e2 = expf(v2 - v1);
        float sm = 1.0f + e2;
        w1s[tid] = 1.0f / sm;
        w2s[tid] = e2 / sm;
        i1s[tid] = i1;
        i2s[tid] = i2;
    }
    __syncthreads();

    // coalesced weight scatter: 32*64 floats = 512 float4
    float4* o4 = reinterpret_cast<float4*>(out + t0 * TE);
    #pragma unroll
    for (int u = 0; u < 2; u++) {
        int idx = u * 256 + tid;
        int m  = idx >> 4;
        int e0 = (idx & 15) << 2;
        int i1 = i1s[m], i2 = i2s[m];
        float w1 = w1s[m], w2 = w2s[m];
        float4 o;
        o.x = (i1 == e0    ) ? w1 : (i2 == e0    ) ? w2 : 0.0f;
        o.y = (i1 == e0 + 1) ? w1 : (i2 == e0 + 1) ? w2 : 0.0f;
        o.z = (i1 == e0 + 2) ? w1 : (i2 == e0 + 2) ? w2 : 0.0f;
        o.w = (i1 == e0 + 3) ? w1 : (i2 == e0 + 3) ? w2 : 0.0f;
        o4[idx] = o;
    }
    if (write_idx && tid < BM) {
        long long t = t0 + tid;
        float* oi = out + (size_t)T * TE;
        oi[t * 2 + 0] = (float)i1s[tid];
        oi[t * 2 + 1] = (float)i2s[tid];
    }
}

extern "C" void kernel_launch(void* const* d_in, const int* in_sizes, int n_in,
                              void* d_out, int out_size) {
    const float* x     = (const float*)d_in[0];
    const float* gw    = (const float*)d_in[1];
    const float* nw    = (const float*)d_in[2];
    const float* noise = (const float*)d_in[3];
    float* out = (float*)d_out;

    int T = in_sizes[0] / TD;                       // 16384
    int write_idx = (out_size >= T * TE + T * 2) ? 1 : 0;

    cudaFuncSetAttribute(gate_kernel, cudaFuncAttributeMaxDynamicSharedMemorySize, SMEM_BYTES);

    wconv_kernel<<<64, 256>>>(gw);
    gate_kernel<<<T / BM, THREADS, SMEM_BYTES>>>(x, nw, noise, out, T, write_idx);
}

// round 17
// speedup vs baseline: 1.2361x; 1.2361x over previous
#include <cuda_runtime.h>
#include <cuda_fp16.h>
#include <math.h>
#include <stdint.h>

#define TD 1024
#define TE 64
#define BM 64            // tokens per CTA (grid = 256)
#define THREADS 256
#define DEPTH 4          // per-warp A ring slots

// smem layout:
//   A ring: wid*4096 + slot*1024, 8 warps x 4KB : 0 .. 32768
//   noiseS [64][64] f32                         : 32768 .. 49152
//   nws [64] f32                                : 49152 .. 49408
//   w1s/w2s/i1s/i2s (64 each)                   : 49408 .. 50432
//   Cs [64][66] f32 (aliases ring post-mainloop): 0 .. 16896
#define CS_OFF    0
#define CS_STRIDE 66
#define NZ_OFF    32768
#define NW_OFF    49152
#define W1_OFF    49408
#define W2_OFF    49664
#define I1_OFF    49920
#define I2_OFF    50176
#define SMEM_BYTES 50432

typedef unsigned int u32;

// W fragments, k-permuted, term-split, ntile-PAIRED:
// [kstep][jpair][lane] -> uint4{ b0(2jp), b1(2jp), b0(2jp+1), b1(2jp+1) }
__device__ uint4 g_wfH[8192];
__device__ uint4 g_wfL[8192];

__device__ __forceinline__ u32 smem_u32(const void* p) {
    u32 a;
    asm("{ .reg .u64 t; cvta.to.shared.u64 t, %1; cvt.u32.u64 %0, t; }" : "=r"(a) : "l"(p));
    return a;
}
// 2 floats -> 2 packed fp16x2 terms (hi, residual-lo)
__device__ __forceinline__ void split2(float vl, float vh, u32& t0, u32& t1) {
    __half2 h0 = __floats2half2_rn(vl, vh);
    float2 f0 = __half22float2(h0);
    __half2 h1 = __floats2half2_rn(vl - f0.x, vh - f0.y);
    t0 = *reinterpret_cast<u32*>(&h0);
    t1 = *reinterpret_cast<u32*>(&h1);
}
__device__ __forceinline__ void mma16816(float* c, const u32* A, u32 b0, u32 b1) {
    asm volatile(
        "mma.sync.aligned.m16n8k16.row.col.f32.f16.f16.f32 "
        "{%0,%1,%2,%3}, {%4,%5,%6,%7}, {%8,%9}, {%0,%1,%2,%3};"
        : "+f"(c[0]), "+f"(c[1]), "+f"(c[2]), "+f"(c[3])
        : "r"(A[0]), "r"(A[1]), "r"(A[2]), "r"(A[3]), "r"(b0), "r"(b1));
}
__device__ __forceinline__ void cp16(u32 dst, const void* src) {
    asm volatile("cp.async.cg.shared.global [%0], [%1], 16;" :: "r"(dst), "l"(src));
}
__device__ __forceinline__ void cp_commit() {
    asm volatile("cp.async.commit_group;" ::: "memory");
}
__device__ __forceinline__ void cp_wait2() {
    asm volatile("cp.async.wait_group 2;" ::: "memory");
}
__device__ __forceinline__ float4 lds128(u32 a) {
    float4 v;
    asm volatile("ld.shared.v4.f32 {%0,%1,%2,%3}, [%4];"
                 : "=f"(v.x), "=f"(v.y), "=f"(v.z), "=f"(v.w) : "r"(a));
    return v;
}

// ---------------- pre-kernel: W fp32 -> k-permuted, ntile-paired fp16x2 fragments ----------------
__global__ void __launch_bounds__(256) wconv_kernel(const float* __restrict__ gw) {
    int t = blockIdx.x * 256 + threadIdx.x;     // 0..8191
    int ks   = t >> 7;                          // 0..63
    int jp   = (t >> 5) & 3;                    // ntile pair 0..3
    int lane = t & 31;
    int n0 = jp * 16 + (lane >> 2);             // ntile 2jp row
    int n1 = n0 + 8;                            // ntile 2jp+1 row
    int k0 = ks * 16 + 4 * (lane & 3);          // 4 contiguous k per lane (pi-permuted)
    float4 p0 = *reinterpret_cast<const float4*>(gw + n0 * TD + k0);
    float4 p1 = *reinterpret_cast<const float4*>(gw + n1 * TD + k0);
    u32 b0h0, b0l0, b1h0, b1l0, b0h1, b0l1, b1h1, b1l1;
    split2(p0.x, p0.y, b0h0, b0l0);
    split2(p0.z, p0.w, b1h0, b1l0);
    split2(p1.x, p1.y, b0h1, b0l1);
    split2(p1.z, p1.w, b1h1, b1l1);
    int idx = ks * 128 + jp * 32 + lane;
    g_wfH[idx] = make_uint4(b0h0, b1h0, b0h1, b1h1);
    g_wfL[idx] = make_uint4(b0l0, b1l0, b0l1, b1l1);
}

// ---------------- main fused kernel ----------------
// warp = 16 tokens x 64 experts x K/2.  8 warps: mtw(4) x kh(2).
__global__ void __launch_bounds__(THREADS, 2) gate_kernel(
    const float* __restrict__ x,      // [T, 1024]
    const float* __restrict__ nw,     // [64]
    const float* __restrict__ noise,  // [T, 64]
    float* __restrict__ out,
    int T, int write_idx)
{
    extern __shared__ char smem[];
    const u32 sb = smem_u32(smem);
    const int tid  = threadIdx.x;
    const int lane = tid & 31;
    const int wid  = tid >> 5;
    const int mtw  = wid & 3;          // token group: tokens mtw*16..+15
    const int kh   = wid >> 2;         // k half: ksteps kh*32..+31
    const long long t0 = (long long)blockIdx.x * BM;

    // --- stage noise + nw into smem (hides epilogue tail) ---
    {
        const float4* np = reinterpret_cast<const float4*>(noise + t0 * TE);
        float4* ns = reinterpret_cast<float4*>(smem + NZ_OFF);
        #pragma unroll
        for (int u = 0; u < 4; u++) ns[u * 256 + tid] = np[u * 256 + tid];
        if (tid < TE) reinterpret_cast<float*>(smem + NW_OFF)[tid] = nw[tid];
    }

    const int kb = kh * 32;            // base kstep for this warp
    // A slot = 64 chunks of 16B; chunk c <-> row c>>2, quad c&3.
    // Lane copies chunks c0=lane (rows 0-7), c1=lane+32 (rows 8-15);
    // reader lane reads exactly its own chunks -> no intra-warp sync needed.
    const int c0 = lane, c1 = lane + 32;
    const float* xsrc0 = x + (t0 + mtw * 16 + (c0 >> 2)) * TD + kb * 16 + (c0 & 3) * 4;
    const float* xsrc1 = x + (t0 + mtw * 16 + 8 + ((c1 - 32) >> 2)) * TD + kb * 16 + (c1 & 3) * 4;
    const u32 ringBase = sb + wid * (DEPTH * 1024);
    const u32 ring0 = ringBase + c0 * 16;
    const u32 ring1 = ringBase + c1 * 16;
    const u32 ldsA = ringBase + (lane >> 2) * 64 + (lane & 3) * 16;
    const uint4* bpH = g_wfH + kb * 128 + lane;
    const uint4* bpL = g_wfL + kb * 128 + lane;

    float acc[8][4];
    #pragma unroll
    for (int i = 0; i < 8; i++)
        #pragma unroll
        for (int j = 0; j < 4; j++) acc[i][j] = 0.0f;

    // prologue: issue A slots 0..2
    #pragma unroll
    for (int p = 0; p < DEPTH - 1; p++) {
        cp16(ring0 + p * 1024, xsrc0 + p * 16);
        cp16(ring1 + p * 1024, xsrc1 + p * 16);
        cp_commit();
    }
    // preload B kstep kb (both terms; 4 uint4 = 8 ntiles per term)
    uint4 bH[4], bL[4];
    #pragma unroll
    for (int j = 0; j < 4; j++) bH[j] = bpH[j * 32];
    #pragma unroll
    for (int j = 0; j < 4; j++) bL[j] = bpL[j * 32];

    #pragma unroll 2
    for (int ks = 0; ks < 32; ks++) {
        cp_wait2();
        const u32 slot = ldsA + (ks & (DEPTH - 1)) * 1024;
        float4 fa = lds128(slot);            // row g,   k quad
        float4 fb = lds128(slot + 8 * 64);   // row g+8, k quad
        if (ks + DEPTH - 1 < 32) {
            cp16(ring0 + ((ks + DEPTH - 1) & (DEPTH - 1)) * 1024, xsrc0 + (ks + DEPTH - 1) * 16);
            cp16(ring1 + ((ks + DEPTH - 1) & (DEPTH - 1)) * 1024, xsrc1 + (ks + DEPTH - 1) * 16);
        }
        cp_commit();
        // convert A (both terms); a0=(g,klo) a1=(g+8,klo) a2=(g,khi) a3=(g+8,khi)
        u32 aH[4], aL[4];
        split2(fa.x, fa.y, aH[0], aL[0]);
        split2(fb.x, fb.y, aH[1], aL[1]);
        split2(fa.z, fa.w, aH[2], aL[2]);
        split2(fb.z, fb.w, aH[3], aL[3]);

        const int nks = (ks + 1) & 31;       // wraps harmlessly on last iter
        // pass 1: hh
        #pragma unroll
        for (int jp = 0; jp < 4; jp++) {
            mma16816(acc[2 * jp],     aH, bH[jp].x, bH[jp].y);
            mma16816(acc[2 * jp + 1], aH, bH[jp].z, bH[jp].w);
        }
        // pass 2: lh — last use of bH(ks)
        #pragma unroll
        for (int jp = 0; jp < 4; jp++) {
            mma16816(acc[2 * jp],     aL, bH[jp].x, bH[jp].y);
            mma16816(acc[2 * jp + 1], aL, bH[jp].z, bH[jp].w);
        }
        // reload bH <- kstep ks+1
        {
            const uint4* bq = bpH + nks * 128;
            #pragma unroll
            for (int j = 0; j < 4; j++) bH[j] = bq[j * 32];
        }
        // pass 3: hl — last use of bL(ks)
        #pragma unroll
        for (int jp = 0; jp < 4; jp++) {
            mma16816(acc[2 * jp],     aH, bL[jp].x, bL[jp].y);
            mma16816(acc[2 * jp + 1], aH, bL[jp].z, bL[jp].w);
        }
        // reload bL <- kstep ks+1
        {
            const uint4* bq = bpL + nks * 128;
            #pragma unroll
            for (int j = 0; j < 4; j++) bL[j] = bq[j * 32];
        }
    }

    // ---------------- split-K reduction + epilogue (Cs aliases ring) ----------------
    __syncthreads();   // all warps done with ring before Cs overwrites it
    float* Cs  = reinterpret_cast<float*>(smem + CS_OFF);
    float* w1s = reinterpret_cast<float*>(smem + W1_OFF);
    float* w2s = reinterpret_cast<float*>(smem + W2_OFF);
    int*   i1s = reinterpret_cast<int*>(smem + I1_OFF);
    int*   i2s = reinterpret_cast<int*>(smem + I2_OFF);
    const float* nzS  = reinterpret_cast<const float*>(smem + NZ_OFF);
    const float* nwsS = reinterpret_cast<const float*>(smem + NW_OFF);

    const int g  = lane >> 2, tq = lane & 3;
    const int r0 = mtw * 16 + g;

    if (kh == 1) {   // warps 4-7 store their partial first
        #pragma unroll
        for (int nt = 0; nt < 8; nt++) {
            int col = nt * 8 + 2 * tq;
            *reinterpret_cast<float2*>(&Cs[r0 * CS_STRIDE + col])       = make_float2(acc[nt][0], acc[nt][1]);
            *reinterpret_cast<float2*>(&Cs[(r0 + 8) * CS_STRIDE + col]) = make_float2(acc[nt][2], acc[nt][3]);
        }
    }
    __syncthreads();
    if (kh == 0) {   // warps 0-3 add theirs
        #pragma unroll
        for (int nt = 0; nt < 8; nt++) {
            int col = nt * 8 + 2 * tq;
            float2* p0 = reinterpret_cast<float2*>(&Cs[r0 * CS_STRIDE + col]);
            float2* p1 = reinterpret_cast<float2*>(&Cs[(r0 + 8) * CS_STRIDE + col]);
            float2 v0 = *p0, v1 = *p1;
            v0.x += acc[nt][0]; v0.y += acc[nt][1];
            v1.x += acc[nt][2]; v1.y += acc[nt][3];
            *p0 = v0; *p1 = v1;
        }
    }
    __syncthreads();

    if (tid < BM) {
        const float* rowp = Cs + tid * CS_STRIDE;
        const float* nr   = nzS + tid * TE;
        float v1 = -3.402823466e38f, v2 = -3.402823466e38f;
        int i1 = 0, i2 = 0;
        #pragma unroll
        for (int e = 0; e < TE; e++) {
            float v = rowp[e] + nr[e] * nwsS[e];
            if (v > v1)      { v2 = v1; i2 = i1; v1 = v; i1 = e; }
            else if (v > v2) { v2 = v;  i2 = e; }
        }
        float e2 = expf(v2 - v1);
        float sm = 1.0f + e2;
        w1s[tid] = 1.0f / sm;
        w2s[tid] = e2 / sm;
        i1s[tid] = i1;
        i2s[tid] = i2;
    }
    __syncthreads();

    // coalesced weight scatter: 64*64 floats = 1024 float4
    float4* o4 = reinterpret_cast<float4*>(out + t0 * TE);
    #pragma unroll
    for (int u = 0; u < 4; u++) {
        int idx = u * 256 + tid;
        int m  = idx >> 4;
        int e0 = (idx & 15) << 2;
        int i1 = i1s[m], i2 = i2s[m];
        float w1 = w1s[m], w2 = w2s[m];
        float4 o;
        o.x = (i1 == e0    ) ? w1 : (i2 == e0    ) ? w2 : 0.0f;
        o.y = (i1 == e0 + 1) ? w1 : (i2 == e0 + 1) ? w2 : 0.0f;
        o.z = (i1 == e0 + 2) ? w1 : (i2 == e0 + 2) ? w2 : 0.0f;
        o.w = (i1 == e0 + 3) ? w1 : (i2 == e0 + 3) ? w2 : 0.0f;
        o4[idx] = o;
    }
    if (write_idx && tid < BM) {
        long long t = t0 + tid;
        float* oi = out + (size_t)T * TE;
        oi[t * 2 + 0] = (float)i1s[tid];
        oi[t * 2 + 1] = (float)i2s[tid];
    }
}

extern "C" void kernel_launch(void* const* d_in, const int* in_sizes, int n_in,
                              void* d_out, int out_size) {
    const float* x     = (const float*)d_in[0];
    const float* gw    = (const float*)d_in[1];
    const float* nw    = (const float*)d_in[2];
    const float* noise = (const float*)d_in[3];
    float* out = (float*)d_out;

    int T = in_sizes[0] / TD;                       // 16384
    int write_idx = (out_size >= T * TE + T * 2) ? 1 : 0;

    cudaFuncSetAttribute(gate_kernel, cudaFuncAttributeMaxDynamicSharedMemorySize, SMEM_BYTES);

    wconv_kernel<<<32, 256>>>(gw);
    gate_kernel<<<T / BM, THREADS, SMEM_BYTES>>>(x, nw, noise, out, T, write_idx);
}